// round 10
// baseline (speedup 1.0000x reference)
#include <cuda_runtime.h>

#define TPB 128
typedef unsigned long long u64;

// ---------------- packed f32x2 helpers (sm_103a) ----------------
__device__ __forceinline__ u64 pk2(float x, float y) {
    u64 r; asm("mov.b64 %0, {%1,%2};" : "=l"(r) : "f"(x), "f"(y)); return r;
}
__device__ __forceinline__ void up2(u64 v, float& x, float& y) {
    asm("mov.b64 {%0,%1}, %2;" : "=f"(x), "=f"(y) : "l"(v));
}
__device__ __forceinline__ u64 fma2_(u64 a, u64 b, u64 c) {
    u64 d; asm("fma.rn.f32x2 %0, %1, %2, %3;" : "=l"(d) : "l"(a), "l"(b), "l"(c)); return d;
}
__device__ __forceinline__ u64 add2_(u64 a, u64 b) {
    u64 d; asm("add.rn.f32x2 %0, %1, %2;" : "=l"(d) : "l"(a), "l"(b)); return d;
}
__device__ __forceinline__ float lrelu(float z) { return fmaxf(z, 0.01f * z); }

// ---------------- constant-bank weight image (31232B: cache-resident) ----------------
#define O_W1    0      // [6][3][16]          288
#define O_B1    288    // [6][16]             96
#define O_W2    384    // [6][16][32]         3072
#define O_TBO   3456   // [32] b2p-b2k_o
#define O_DTB   3488   // [32] b2k_o-b2k_c
#define O_UB    3520   // [2][32] b2p+b2v
#define O_BQ    3584   // [32]  b2 of q
#define O_WP1T  3616   // [64][32] transposed 2048
#define O_WPB1  5664   // [64]
#define O_WP2   5728   // [64][32]            2048
#define O_WPB2  7776   // [32]
#define N_CONST 7808

__constant__ __align__(16) float c_all[N_CONST];
__device__   __align__(16) float g_prep[N_CONST];

// ---------------- prep ----------------
__global__ void prep_kernel(const float* __restrict__ w1, const float* __restrict__ b1,
                            const float* __restrict__ w2, const float* __restrict__ b2,
                            const float* __restrict__ wp1, const float* __restrict__ wpb1,
                            const float* __restrict__ wp2, const float* __restrict__ wpb2) {
    const int t = threadIdx.x;
    for (int i = t; i < 288;  i += 256) g_prep[O_W1 + i] = w1[i];
    for (int i = t; i < 96;   i += 256) g_prep[O_B1 + i] = b1[i];
    for (int i = t; i < 3072; i += 256) g_prep[O_W2 + i] = w2[i];
    for (int i = t; i < 32;   i += 256) {
        float bp = b2[5 * 32 + i];
        g_prep[O_TBO + i]     = bp - b2[3 * 32 + i];
        g_prep[O_DTB + i]     = b2[3 * 32 + i] - b2[1 * 32 + i];
        g_prep[O_UB + i]      = bp + b2[2 * 32 + i];
        g_prep[O_UB + 32 + i] = bp + b2[4 * 32 + i];
        g_prep[O_BQ + i]      = b2[i];
        g_prep[O_WPB2 + i]    = wpb2[i];
    }
    for (int i = t; i < 2048; i += 256) {
        int c = i >> 6, j = i & 63;              // wp1 is [32][64]
        g_prep[O_WP1T + j * 32 + c] = wp1[i];
        g_prep[O_WP2 + i] = wp2[i];
    }
    for (int i = t; i < 64;   i += 256) g_prep[O_WPB1 + i] = wpb1[i];
}

// ---------------- softmax over channels + weighted accumulate ----------------
__device__ __forceinline__ void softmax_acc(
    const u64* __restrict__ fw2, const u64 (*s_u)[TPB], int uoff,
    u64 (*s_acc)[TPB], int tid)
{
    float f[32];
    #pragma unroll
    for (int i = 0; i < 16; ++i) up2(fw2[i], f[2 * i], f[2 * i + 1]);
    float m0 = f[0], m1 = f[1], m2 = f[2], m3 = f[3];
    #pragma unroll
    for (int c = 4; c < 32; c += 4) {
        m0 = fmaxf(m0, f[c + 0]); m1 = fmaxf(m1, f[c + 1]);
        m2 = fmaxf(m2, f[c + 2]); m3 = fmaxf(m3, f[c + 3]);
    }
    float m = fmaxf(fmaxf(m0, m1), fmaxf(m2, m3));
    float s0 = 0.f, s1 = 0.f, s2 = 0.f, s3 = 0.f;
    #pragma unroll
    for (int c = 0; c < 32; c += 4) {
        f[c + 0] = __expf(f[c + 0] - m); s0 += f[c + 0];
        f[c + 1] = __expf(f[c + 1] - m); s1 += f[c + 1];
        f[c + 2] = __expf(f[c + 2] - m); s2 += f[c + 2];
        f[c + 3] = __expf(f[c + 3] - m); s3 += f[c + 3];
    }
    float inv = __fdividef(1.0f, (s0 + s1) + (s2 + s3));
    #pragma unroll
    for (int i = 0; i < 16; ++i)
        s_acc[i][tid] = fma2_(pk2(f[2 * i] * inv, f[2 * i + 1] * inv),
                              s_u[uoff + i][tid], s_acc[i][tid]);
}

// ---------------- center row (solo, MLP1/2) ----------------
__device__ __forceinline__ void do_center(
    float x0, float x1, float x2,
    const u64 (*s_q)[TPB], u64 (*s_u)[TPB], u64 (*s_acc)[TPB], int tid)
{
    u64 t2[16], u2[16];
    {
        const u64* dtb = (const u64*)&c_all[O_DTB];
        const u64* ub  = (const u64*)&c_all[O_UB];
        #pragma unroll
        for (int i = 0; i < 16; ++i) {
            t2[i] = add2_(s_q[i][tid], dtb[i]);
            u2[i] = ub[i];
        }
    }
    const float* w1k = &c_all[O_W1 + 1 * 48];
    const float* w1v = &c_all[O_W1 + 2 * 48];
    #pragma unroll 1
    for (int j = 0; j < 16; ++j) {
        float zk = c_all[O_B1 + 16 + j] + x0 * w1k[j] + x1 * w1k[16 + j] + x2 * w1k[32 + j];
        float zv = c_all[O_B1 + 32 + j] + x0 * w1v[j] + x1 * w1v[16 + j] + x2 * w1v[32 + j];
        float zp = c_all[O_B1 + 80 + j];           // fea_minus = 0 for center
        float hk = lrelu(zk), hv = lrelu(zv), hp = lrelu(zp);
        u64 nhk2 = pk2(-hk, -hk), hv2 = pk2(hv, hv), hp2 = pk2(hp, hp);
        const ulonglong2* wk = (const ulonglong2*)&c_all[O_W2 + (1 * 16 + j) * 32];
        const ulonglong2* wv = (const ulonglong2*)&c_all[O_W2 + (2 * 16 + j) * 32];
        const ulonglong2* wp = (const ulonglong2*)&c_all[O_W2 + (5 * 16 + j) * 32];
        #pragma unroll
        for (int i2 = 0; i2 < 8; ++i2) {
            ulonglong2 kw = wk[i2], vw = wv[i2], pw = wp[i2];
            t2[2 * i2]     = fma2_(nhk2, kw.x, fma2_(hp2, pw.x, t2[2 * i2]));
            t2[2 * i2 + 1] = fma2_(nhk2, kw.y, fma2_(hp2, pw.y, t2[2 * i2 + 1]));
            u2[2 * i2]     = fma2_(hv2,  vw.x, fma2_(hp2, pw.x, u2[2 * i2]));
            u2[2 * i2 + 1] = fma2_(hv2,  vw.y, fma2_(hp2, pw.y, u2[2 * i2 + 1]));
        }
    }
    #pragma unroll
    for (int i = 0; i < 16; ++i) s_u[i][tid] = u2[i];

    u64 fw2[16];
    {
        const u64* wb = (const u64*)&c_all[O_WPB2];
        #pragma unroll
        for (int i = 0; i < 16; ++i) fw2[i] = wb[i];
    }
    #pragma unroll 1
    for (int j = 0; j < 64; ++j) {
        const ulonglong2* w1t = (const ulonglong2*)&c_all[O_WP1T + j * 32];
        u64 za = 0ull, zb = 0ull;
        #pragma unroll
        for (int i2 = 0; i2 < 8; ++i2) {
            ulonglong2 w = w1t[i2];
            za = fma2_(t2[2 * i2],     w.x, za);
            zb = fma2_(t2[2 * i2 + 1], w.y, zb);
        }
        float a0, a1, b0, b1;
        up2(za, a0, a1); up2(zb, b0, b1);
        float z = c_all[O_WPB1 + j] + ((a0 + b0) + (a1 + b1));
        float g = lrelu(z);
        u64 g2 = pk2(g, g);
        const ulonglong2* w2r = (const ulonglong2*)&c_all[O_WP2 + j * 32];
        #pragma unroll
        for (int i2 = 0; i2 < 8; ++i2) {
            ulonglong2 w = w2r[i2];
            fw2[2 * i2]     = fma2_(g2, w.x, fw2[2 * i2]);
            fw2[2 * i2 + 1] = fma2_(g2, w.y, fw2[2 * i2 + 1]);
        }
    }
    softmax_acc(fw2, s_u, 0, s_acc, tid);
}

// ---------------- neighbor row PAIR (MLP3/4; weights loaded once, used twice) ----------------
__device__ __forceinline__ void do_pair(
    float xa0, float xa1, float xa2, float da0, float da1, float da2,
    float xb0, float xb1, float xb2, float db0, float db1, float db2,
    const u64 (*s_q)[TPB], u64 (*s_u)[TPB], u64 (*s_acc)[TPB], int tid)
{
    u64 t2a[16], t2b[16], u2a[16], u2b[16];
    {
        const u64* ub = (const u64*)&c_all[O_UB + 32];
        #pragma unroll
        for (int i = 0; i < 16; ++i) {
            u64 qv = s_q[i][tid], uv = ub[i];
            t2a[i] = qv; t2b[i] = qv;
            u2a[i] = uv; u2b[i] = uv;
        }
    }

    // ---- hidden loop: shared 16B weight loads drive both rows ----
    const float* w1k = &c_all[O_W1 + 3 * 48];
    const float* w1v = &c_all[O_W1 + 4 * 48];
    const float* w1p = &c_all[O_W1 + 5 * 48];
    #pragma unroll 1
    for (int j = 0; j < 16; ++j) {
        float k0 = w1k[j], k1 = w1k[16 + j], k2 = w1k[32 + j], bk = c_all[O_B1 + 48 + j];
        float v0 = w1v[j], v1 = w1v[16 + j], v2 = w1v[32 + j], bv = c_all[O_B1 + 64 + j];
        float p0 = w1p[j], p1 = w1p[16 + j], p2 = w1p[32 + j], bp = c_all[O_B1 + 80 + j];
        float hka = lrelu(bk + xa0 * k0 + xa1 * k1 + xa2 * k2);
        float hkb = lrelu(bk + xb0 * k0 + xb1 * k1 + xb2 * k2);
        float hva = lrelu(bv + xa0 * v0 + xa1 * v1 + xa2 * v2);
        float hvb = lrelu(bv + xb0 * v0 + xb1 * v1 + xb2 * v2);
        float hpa = lrelu(bp + da0 * p0 + da1 * p1 + da2 * p2);
        float hpb = lrelu(bp + db0 * p0 + db1 * p1 + db2 * p2);
        u64 nhka2 = pk2(-hka, -hka), nhkb2 = pk2(-hkb, -hkb);
        u64 hva2  = pk2(hva, hva),   hvb2  = pk2(hvb, hvb);
        u64 hpa2  = pk2(hpa, hpa),   hpb2  = pk2(hpb, hpb);
        const ulonglong2* wk = (const ulonglong2*)&c_all[O_W2 + (3 * 16 + j) * 32];
        const ulonglong2* wv = (const ulonglong2*)&c_all[O_W2 + (4 * 16 + j) * 32];
        const ulonglong2* wp = (const ulonglong2*)&c_all[O_W2 + (5 * 16 + j) * 32];
        #pragma unroll
        for (int i2 = 0; i2 < 8; ++i2) {
            ulonglong2 kw = wk[i2], vw = wv[i2], pw = wp[i2];
            t2a[2 * i2]     = fma2_(nhka2, kw.x, fma2_(hpa2, pw.x, t2a[2 * i2]));
            t2a[2 * i2 + 1] = fma2_(nhka2, kw.y, fma2_(hpa2, pw.y, t2a[2 * i2 + 1]));
            t2b[2 * i2]     = fma2_(nhkb2, kw.x, fma2_(hpb2, pw.x, t2b[2 * i2]));
            t2b[2 * i2 + 1] = fma2_(nhkb2, kw.y, fma2_(hpb2, pw.y, t2b[2 * i2 + 1]));
            u2a[2 * i2]     = fma2_(hva2,  vw.x, fma2_(hpa2, pw.x, u2a[2 * i2]));
            u2a[2 * i2 + 1] = fma2_(hva2,  vw.y, fma2_(hpa2, pw.y, u2a[2 * i2 + 1]));
            u2b[2 * i2]     = fma2_(hvb2,  vw.x, fma2_(hpb2, pw.x, u2b[2 * i2]));
            u2b[2 * i2 + 1] = fma2_(hvb2,  vw.y, fma2_(hpb2, pw.y, u2b[2 * i2 + 1]));
        }
    }

    // park u for both rows; frees 64 regs for the WP phase
    #pragma unroll
    for (int i = 0; i < 16; ++i) { s_u[i][tid] = u2a[i]; s_u[16 + i][tid] = u2b[i]; }

    // ---- WP: 32 -> 64 (leaky) -> 32, shared 16B weight loads for both rows ----
    u64 fwa[16], fwb[16];
    {
        const u64* wb = (const u64*)&c_all[O_WPB2];
        #pragma unroll
        for (int i = 0; i < 16; ++i) { fwa[i] = wb[i]; fwb[i] = wb[i]; }
    }
    #pragma unroll 1
    for (int j = 0; j < 64; ++j) {
        const ulonglong2* w1t = (const ulonglong2*)&c_all[O_WP1T + j * 32];
        u64 za0 = 0ull, za1 = 0ull, zb0 = 0ull, zb1 = 0ull;
        #pragma unroll
        for (int i2 = 0; i2 < 8; ++i2) {
            ulonglong2 w = w1t[i2];
            za0 = fma2_(t2a[2 * i2],     w.x, za0);
            za1 = fma2_(t2a[2 * i2 + 1], w.y, za1);
            zb0 = fma2_(t2b[2 * i2],     w.x, zb0);
            zb1 = fma2_(t2b[2 * i2 + 1], w.y, zb1);
        }
        float p0, p1, p2, p3, q0, q1, q2, q3;
        up2(za0, p0, p1); up2(za1, p2, p3);
        up2(zb0, q0, q1); up2(zb1, q2, q3);
        float bj = c_all[O_WPB1 + j];
        float ga = lrelu(bj + ((p0 + p2) + (p1 + p3)));
        float gb = lrelu(bj + ((q0 + q2) + (q1 + q3)));
        u64 ga2 = pk2(ga, ga), gb2 = pk2(gb, gb);
        const ulonglong2* w2r = (const ulonglong2*)&c_all[O_WP2 + j * 32];
        #pragma unroll
        for (int i2 = 0; i2 < 8; ++i2) {
            ulonglong2 w = w2r[i2];
            fwa[2 * i2]     = fma2_(ga2, w.x, fwa[2 * i2]);
            fwa[2 * i2 + 1] = fma2_(ga2, w.y, fwa[2 * i2 + 1]);
            fwb[2 * i2]     = fma2_(gb2, w.x, fwb[2 * i2]);
            fwb[2 * i2 + 1] = fma2_(gb2, w.y, fwb[2 * i2 + 1]);
        }
    }

    softmax_acc(fwa, s_u, 0,  s_acc, tid);
    softmax_acc(fwb, s_u, 16, s_acc, tid);
}

// ---------------- main kernel: one thread per point, dynamic smem ----------------
__global__ void __launch_bounds__(TPB, 3) pae_kernel(
    const float* __restrict__ g_center,   // [P,1,3]
    const float* __restrict__ g_other,    // [P,16,3]
    float* __restrict__ g_out,            // [P,32]
    int P)
{
    extern __shared__ u64 dyn[];
    u64 (*s_q)[TPB]   = (u64(*)[TPB])(dyn);             // [16][TPB]  parked q'=q+tbo
    u64 (*s_u)[TPB]   = (u64(*)[TPB])(dyn + 16 * TPB);  // [32][TPB]  u for row a,b
    u64 (*s_acc)[TPB] = (u64(*)[TPB])(dyn + 48 * TPB);  // [16][TPB]  output acc

    const int tid = threadIdx.x;
    const int p = blockIdx.x * TPB + tid;
    if (p >= P) return;

    const float cx = g_center[p * 3 + 0];
    const float cy = g_center[p * 3 + 1];
    const float cz = g_center[p * 3 + 2];

    // ---- q' = MLP0(center) + tbo, parked in smem ----
    {
        u64 q2[16];
        const u64* bq = (const u64*)&c_all[O_BQ];
        #pragma unroll
        for (int i = 0; i < 16; ++i) q2[i] = bq[i];
        #pragma unroll 1
        for (int j = 0; j < 16; ++j) {
            float z = c_all[O_B1 + j] + cx * c_all[O_W1 + j] + cy * c_all[O_W1 + 16 + j]
                                      + cz * c_all[O_W1 + 32 + j];
            float h = lrelu(z);
            u64 h2 = pk2(h, h);
            const ulonglong2* w = (const ulonglong2*)&c_all[O_W2 + j * 32];
            #pragma unroll
            for (int i2 = 0; i2 < 8; ++i2) {
                ulonglong2 a = w[i2];
                q2[2 * i2]     = fma2_(h2, a.x, q2[2 * i2]);
                q2[2 * i2 + 1] = fma2_(h2, a.y, q2[2 * i2 + 1]);
            }
        }
        const u64* tb = (const u64*)&c_all[O_TBO];
        #pragma unroll
        for (int i = 0; i < 16; ++i) s_q[i][tid] = add2_(q2[i], tb[i]);
    }

    #pragma unroll
    for (int i = 0; i < 16; ++i) s_acc[i][tid] = 0ull;

    // ---- center row ----
    do_center(cx, cy, cz, s_q, s_u, s_acc, tid);

    // ---- 8 pairs of neighbor rows ----
    const float* obase = g_other + p * 48;
    for (int r = 0; r < 16; r += 2) {
        const float* oa = obase + r * 3;
        float xa0 = oa[0], xa1 = oa[1], xa2 = oa[2];
        float xb0 = oa[3], xb1 = oa[4], xb2 = oa[5];
        do_pair(xa0, xa1, xa2, cx - xa0, cy - xa1, cz - xa2,
                xb0, xb1, xb2, cx - xb0, cy - xb1, cz - xb2,
                s_q, s_u, s_acc, tid);
    }

    // ---- store [32] ----
    ulonglong2* outp = (ulonglong2*)&g_out[p * 32];
    #pragma unroll
    for (int i = 0; i < 8; ++i)
        outp[i] = make_ulonglong2(s_acc[2 * i][tid], s_acc[2 * i + 1][tid]);
}

#define SMEM_BYTES (64 * TPB * 8)   // 65536

extern "C" void kernel_launch(void* const* d_in, const int* in_sizes, int n_in,
                              void* d_out, int out_size) {
    const float* center = (const float*)d_in[0];
    const float* other  = (const float*)d_in[1];
    const float* w1     = (const float*)d_in[2];
    const float* b1     = (const float*)d_in[3];
    const float* w2     = (const float*)d_in[4];
    const float* b2     = (const float*)d_in[5];
    const float* wp1    = (const float*)d_in[6];
    const float* wpb1   = (const float*)d_in[7];
    const float* wp2    = (const float*)d_in[8];
    const float* wpb2   = (const float*)d_in[9];
    float* out = (float*)d_out;

    const int P = in_sizes[0] / 3;

    prep_kernel<<<1, 256>>>(w1, b1, w2, b2, wp1, wpb1, wp2, wpb2);

    void* prep_addr = nullptr;
    cudaGetSymbolAddress(&prep_addr, g_prep);
    cudaMemcpyToSymbolAsync(c_all, prep_addr, N_CONST * sizeof(float), 0,
                            cudaMemcpyDeviceToDevice, 0);

    static bool attr_set = false;
    if (!attr_set) {
        cudaFuncSetAttribute(pae_kernel, cudaFuncAttributeMaxDynamicSharedMemorySize, SMEM_BYTES);
        attr_set = true;
    }
    const int grid = (P + TPB - 1) / TPB;
    pae_kernel<<<grid, TPB, SMEM_BYTES>>>(center, other, out, P);
}

// round 12
// speedup vs baseline: 1.1223x; 1.1223x over previous
#include <cuda_runtime.h>

#define TPB 128
typedef unsigned long long u64;

// ---------------- packed f32x2 helpers (sm_103a) ----------------
__device__ __forceinline__ u64 pk2(float x, float y) {
    u64 r; asm("mov.b64 %0, {%1,%2};" : "=l"(r) : "f"(x), "f"(y)); return r;
}
__device__ __forceinline__ void up2(u64 v, float& x, float& y) {
    asm("mov.b64 {%0,%1}, %2;" : "=f"(x), "=f"(y) : "l"(v));
}
__device__ __forceinline__ u64 fma2_(u64 a, u64 b, u64 c) {
    u64 d; asm("fma.rn.f32x2 %0, %1, %2, %3;" : "=l"(d) : "l"(a), "l"(b), "l"(c)); return d;
}
__device__ __forceinline__ u64 add2_(u64 a, u64 b) {
    u64 d; asm("add.rn.f32x2 %0, %1, %2;" : "=l"(d) : "l"(a), "l"(b)); return d;
}
__device__ __forceinline__ float lrelu(float z) { return fmaxf(z, 0.01f * z); }

// ---------------- constant-bank weight image (31232B: cache-resident) ----------------
#define O_W1    0      // [6][3][16]          288
#define O_B1    288    // [6][16]             96
#define O_W2    384    // [6][16][32]         3072
#define O_TBO   3456   // [32] b2p-b2k_o
#define O_DTB   3488   // [32] b2k_o-b2k_c
#define O_UB    3520   // [2][32] b2p+b2v
#define O_BQ    3584   // [32]  b2 of q
#define O_WP1T  3616   // [64][32] transposed 2048
#define O_WPB1  5664   // [64]
#define O_WP2   5728   // [64][32]            2048
#define O_WPB2  7776   // [32]
#define N_CONST 7808

__constant__ __align__(16) float c_all[N_CONST];
__device__   __align__(16) float g_prep[N_CONST];

// ---------------- prep ----------------
__global__ void prep_kernel(const float* __restrict__ w1, const float* __restrict__ b1,
                            const float* __restrict__ w2, const float* __restrict__ b2,
                            const float* __restrict__ wp1, const float* __restrict__ wpb1,
                            const float* __restrict__ wp2, const float* __restrict__ wpb2) {
    const int t = threadIdx.x;
    for (int i = t; i < 288;  i += 256) g_prep[O_W1 + i] = w1[i];
    for (int i = t; i < 96;   i += 256) g_prep[O_B1 + i] = b1[i];
    for (int i = t; i < 3072; i += 256) g_prep[O_W2 + i] = w2[i];
    for (int i = t; i < 32;   i += 256) {
        float bp = b2[5 * 32 + i];
        g_prep[O_TBO + i]     = bp - b2[3 * 32 + i];
        g_prep[O_DTB + i]     = b2[3 * 32 + i] - b2[1 * 32 + i];
        g_prep[O_UB + i]      = bp + b2[2 * 32 + i];
        g_prep[O_UB + 32 + i] = bp + b2[4 * 32 + i];
        g_prep[O_BQ + i]      = b2[i];
        g_prep[O_WPB2 + i]    = wpb2[i];
    }
    for (int i = t; i < 2048; i += 256) {
        int c = i >> 6, j = i & 63;              // wp1 is [32][64]
        g_prep[O_WP1T + j * 32 + c] = wp1[i];
        g_prep[O_WP2 + i] = wp2[i];
    }
    for (int i = t; i < 64;   i += 256) g_prep[O_WPB1 + i] = wpb1[i];
}

// ---------------- softmax over channels + weighted accumulate ----------------
__device__ __forceinline__ void softmax_acc(
    const u64* __restrict__ fw2, const u64 (*s_u)[TPB], int uoff,
    u64 (*s_acc)[TPB], int tid)
{
    float f[32];
    #pragma unroll
    for (int i = 0; i < 16; ++i) up2(fw2[i], f[2 * i], f[2 * i + 1]);
    float m0 = f[0], m1 = f[1], m2 = f[2], m3 = f[3];
    #pragma unroll
    for (int c = 4; c < 32; c += 4) {
        m0 = fmaxf(m0, f[c + 0]); m1 = fmaxf(m1, f[c + 1]);
        m2 = fmaxf(m2, f[c + 2]); m3 = fmaxf(m3, f[c + 3]);
    }
    float m = fmaxf(fmaxf(m0, m1), fmaxf(m2, m3));
    float s0 = 0.f, s1 = 0.f, s2 = 0.f, s3 = 0.f;
    #pragma unroll
    for (int c = 0; c < 32; c += 4) {
        f[c + 0] = __expf(f[c + 0] - m); s0 += f[c + 0];
        f[c + 1] = __expf(f[c + 1] - m); s1 += f[c + 1];
        f[c + 2] = __expf(f[c + 2] - m); s2 += f[c + 2];
        f[c + 3] = __expf(f[c + 3] - m); s3 += f[c + 3];
    }
    float inv = __fdividef(1.0f, (s0 + s1) + (s2 + s3));
    #pragma unroll
    for (int i = 0; i < 16; ++i)
        s_acc[i][tid] = fma2_(pk2(f[2 * i] * inv, f[2 * i + 1] * inv),
                              s_u[uoff + i][tid], s_acc[i][tid]);
}

// ---------------- center row (solo, MLP1/2) ----------------
__device__ __forceinline__ void do_center(
    float x0, float x1, float x2,
    const u64 (*s_q)[TPB], u64 (*s_u)[TPB], u64 (*s_acc)[TPB], int tid)
{
    u64 t2[16], u2[16];
    {
        const u64* dtb = (const u64*)&c_all[O_DTB];
        const u64* ub  = (const u64*)&c_all[O_UB];
        #pragma unroll
        for (int i = 0; i < 16; ++i) {
            t2[i] = add2_(s_q[i][tid], dtb[i]);
            u2[i] = ub[i];
        }
    }
    const float* w1k = &c_all[O_W1 + 1 * 48];
    const float* w1v = &c_all[O_W1 + 2 * 48];
    #pragma unroll 1
    for (int j = 0; j < 16; ++j) {
        float zk = c_all[O_B1 + 16 + j] + x0 * w1k[j] + x1 * w1k[16 + j] + x2 * w1k[32 + j];
        float zv = c_all[O_B1 + 32 + j] + x0 * w1v[j] + x1 * w1v[16 + j] + x2 * w1v[32 + j];
        float zp = c_all[O_B1 + 80 + j];           // fea_minus = 0 for center
        float hk = lrelu(zk), hv = lrelu(zv), hp = lrelu(zp);
        u64 nhk2 = pk2(-hk, -hk), hv2 = pk2(hv, hv), hp2 = pk2(hp, hp);
        const ulonglong2* wk = (const ulonglong2*)&c_all[O_W2 + (1 * 16 + j) * 32];
        const ulonglong2* wv = (const ulonglong2*)&c_all[O_W2 + (2 * 16 + j) * 32];
        const ulonglong2* wp = (const ulonglong2*)&c_all[O_W2 + (5 * 16 + j) * 32];
        #pragma unroll
        for (int i2 = 0; i2 < 8; ++i2) {
            ulonglong2 kw = wk[i2], vw = wv[i2], pw = wp[i2];
            t2[2 * i2]     = fma2_(nhk2, kw.x, fma2_(hp2, pw.x, t2[2 * i2]));
            t2[2 * i2 + 1] = fma2_(nhk2, kw.y, fma2_(hp2, pw.y, t2[2 * i2 + 1]));
            u2[2 * i2]     = fma2_(hv2,  vw.x, fma2_(hp2, pw.x, u2[2 * i2]));
            u2[2 * i2 + 1] = fma2_(hv2,  vw.y, fma2_(hp2, pw.y, u2[2 * i2 + 1]));
        }
    }
    #pragma unroll
    for (int i = 0; i < 16; ++i) s_u[i][tid] = u2[i];

    u64 fw2[16];
    {
        const u64* wb = (const u64*)&c_all[O_WPB2];
        #pragma unroll
        for (int i = 0; i < 16; ++i) fw2[i] = wb[i];
    }
    #pragma unroll 1
    for (int j = 0; j < 64; ++j) {
        const ulonglong2* w1t = (const ulonglong2*)&c_all[O_WP1T + j * 32];
        u64 za = 0ull, zb = 0ull;
        #pragma unroll
        for (int i2 = 0; i2 < 8; ++i2) {
            ulonglong2 w = w1t[i2];
            za = fma2_(t2[2 * i2],     w.x, za);
            zb = fma2_(t2[2 * i2 + 1], w.y, zb);
        }
        float a0, a1, b0, b1;
        up2(za, a0, a1); up2(zb, b0, b1);
        float z = c_all[O_WPB1 + j] + ((a0 + b0) + (a1 + b1));
        float g = lrelu(z);
        u64 g2 = pk2(g, g);
        const ulonglong2* w2r = (const ulonglong2*)&c_all[O_WP2 + j * 32];
        #pragma unroll
        for (int i2 = 0; i2 < 8; ++i2) {
            ulonglong2 w = w2r[i2];
            fw2[2 * i2]     = fma2_(g2, w.x, fw2[2 * i2]);
            fw2[2 * i2 + 1] = fma2_(g2, w.y, fw2[2 * i2 + 1]);
        }
    }
    softmax_acc(fw2, s_u, 0, s_acc, tid);
}

// ---------------- neighbor row PAIR (MLP3/4; weights loaded once, used twice) ----------------
__device__ __forceinline__ void do_pair(
    float xa0, float xa1, float xa2, float da0, float da1, float da2,
    float xb0, float xb1, float xb2, float db0, float db1, float db2,
    const u64 (*s_q)[TPB], u64 (*s_u)[TPB], u64 (*s_acc)[TPB], int tid)
{
    u64 t2a[16], t2b[16], u2a[16], u2b[16];
    {
        const u64* ub = (const u64*)&c_all[O_UB + 32];
        #pragma unroll
        for (int i = 0; i < 16; ++i) {
            u64 qv = s_q[i][tid], uv = ub[i];
            t2a[i] = qv; t2b[i] = qv;
            u2a[i] = uv; u2b[i] = uv;
        }
    }

    // ---- hidden loop: shared 16B weight loads drive both rows ----
    const float* w1k = &c_all[O_W1 + 3 * 48];
    const float* w1v = &c_all[O_W1 + 4 * 48];
    const float* w1p = &c_all[O_W1 + 5 * 48];
    #pragma unroll 1
    for (int j = 0; j < 16; ++j) {
        float k0 = w1k[j], k1 = w1k[16 + j], k2 = w1k[32 + j], bk = c_all[O_B1 + 48 + j];
        float v0 = w1v[j], v1 = w1v[16 + j], v2 = w1v[32 + j], bv = c_all[O_B1 + 64 + j];
        float p0 = w1p[j], p1 = w1p[16 + j], p2 = w1p[32 + j], bp = c_all[O_B1 + 80 + j];
        float hka = lrelu(bk + xa0 * k0 + xa1 * k1 + xa2 * k2);
        float hkb = lrelu(bk + xb0 * k0 + xb1 * k1 + xb2 * k2);
        float hva = lrelu(bv + xa0 * v0 + xa1 * v1 + xa2 * v2);
        float hvb = lrelu(bv + xb0 * v0 + xb1 * v1 + xb2 * v2);
        float hpa = lrelu(bp + da0 * p0 + da1 * p1 + da2 * p2);
        float hpb = lrelu(bp + db0 * p0 + db1 * p1 + db2 * p2);
        u64 nhka2 = pk2(-hka, -hka), nhkb2 = pk2(-hkb, -hkb);
        u64 hva2  = pk2(hva, hva),   hvb2  = pk2(hvb, hvb);
        u64 hpa2  = pk2(hpa, hpa),   hpb2  = pk2(hpb, hpb);
        const ulonglong2* wk = (const ulonglong2*)&c_all[O_W2 + (3 * 16 + j) * 32];
        const ulonglong2* wv = (const ulonglong2*)&c_all[O_W2 + (4 * 16 + j) * 32];
        const ulonglong2* wp = (const ulonglong2*)&c_all[O_W2 + (5 * 16 + j) * 32];
        #pragma unroll
        for (int i2 = 0; i2 < 8; ++i2) {
            ulonglong2 kw = wk[i2], vw = wv[i2], pw = wp[i2];
            t2a[2 * i2]     = fma2_(nhka2, kw.x, fma2_(hpa2, pw.x, t2a[2 * i2]));
            t2a[2 * i2 + 1] = fma2_(nhka2, kw.y, fma2_(hpa2, pw.y, t2a[2 * i2 + 1]));
            t2b[2 * i2]     = fma2_(nhkb2, kw.x, fma2_(hpb2, pw.x, t2b[2 * i2]));
            t2b[2 * i2 + 1] = fma2_(nhkb2, kw.y, fma2_(hpb2, pw.y, t2b[2 * i2 + 1]));
            u2a[2 * i2]     = fma2_(hva2,  vw.x, fma2_(hpa2, pw.x, u2a[2 * i2]));
            u2a[2 * i2 + 1] = fma2_(hva2,  vw.y, fma2_(hpa2, pw.y, u2a[2 * i2 + 1]));
            u2b[2 * i2]     = fma2_(hvb2,  vw.x, fma2_(hpb2, pw.x, u2b[2 * i2]));
            u2b[2 * i2 + 1] = fma2_(hvb2,  vw.y, fma2_(hpb2, pw.y, u2b[2 * i2 + 1]));
        }
    }

    // park u for both rows
    #pragma unroll
    for (int i = 0; i < 16; ++i) { s_u[i][tid] = u2a[i]; s_u[16 + i][tid] = u2b[i]; }

    // ---- WP: 32 -> 64 (leaky) -> 32, shared 16B weight loads for both rows ----
    u64 fwa[16], fwb[16];
    {
        const u64* wb = (const u64*)&c_all[O_WPB2];
        #pragma unroll
        for (int i = 0; i < 16; ++i) { fwa[i] = wb[i]; fwb[i] = wb[i]; }
    }
    #pragma unroll 1
    for (int j = 0; j < 64; ++j) {
        const ulonglong2* w1t = (const ulonglong2*)&c_all[O_WP1T + j * 32];
        u64 za0 = 0ull, za1 = 0ull, zb0 = 0ull, zb1 = 0ull;
        #pragma unroll
        for (int i2 = 0; i2 < 8; ++i2) {
            ulonglong2 w = w1t[i2];
            za0 = fma2_(t2a[2 * i2],     w.x, za0);
            za1 = fma2_(t2a[2 * i2 + 1], w.y, za1);
            zb0 = fma2_(t2b[2 * i2],     w.x, zb0);
            zb1 = fma2_(t2b[2 * i2 + 1], w.y, zb1);
        }
        float p0, p1, p2, p3, q0, q1, q2, q3;
        up2(za0, p0, p1); up2(za1, p2, p3);
        up2(zb0, q0, q1); up2(zb1, q2, q3);
        float bj = c_all[O_WPB1 + j];
        float ga = lrelu(bj + ((p0 + p2) + (p1 + p3)));
        float gb = lrelu(bj + ((q0 + q2) + (q1 + q3)));
        u64 ga2 = pk2(ga, ga), gb2 = pk2(gb, gb);
        const ulonglong2* w2r = (const ulonglong2*)&c_all[O_WP2 + j * 32];
        #pragma unroll
        for (int i2 = 0; i2 < 8; ++i2) {
            ulonglong2 w = w2r[i2];
            fwa[2 * i2]     = fma2_(ga2, w.x, fwa[2 * i2]);
            fwa[2 * i2 + 1] = fma2_(ga2, w.y, fwa[2 * i2 + 1]);
            fwb[2 * i2]     = fma2_(gb2, w.x, fwb[2 * i2]);
            fwb[2 * i2 + 1] = fma2_(gb2, w.y, fwb[2 * i2 + 1]);
        }
    }

    softmax_acc(fwa, s_u, 0,  s_acc, tid);
    softmax_acc(fwb, s_u, 16, s_acc, tid);
}

// ---------------- main kernel: one thread per point, 2 blocks/SM (no spills) ----------------
__global__ void __launch_bounds__(TPB, 2) pae_kernel(
    const float* __restrict__ g_center,   // [P,1,3]
    const float* __restrict__ g_other,    // [P,16,3]
    float* __restrict__ g_out,            // [P,32]
    int P)
{
    extern __shared__ u64 dyn[];
    u64 (*s_q)[TPB]   = (u64(*)[TPB])(dyn);             // [16][TPB]  parked q'=q+tbo
    u64 (*s_u)[TPB]   = (u64(*)[TPB])(dyn + 16 * TPB);  // [32][TPB]  u for row a,b
    u64 (*s_acc)[TPB] = (u64(*)[TPB])(dyn + 48 * TPB);  // [16][TPB]  output acc

    const int tid = threadIdx.x;
    const int p = blockIdx.x * TPB + tid;
    if (p >= P) return;

    const float cx = g_center[p * 3 + 0];
    const float cy = g_center[p * 3 + 1];
    const float cz = g_center[p * 3 + 2];

    // ---- q' = MLP0(center) + tbo, parked in smem ----
    {
        u64 q2[16];
        const u64* bq = (const u64*)&c_all[O_BQ];
        #pragma unroll
        for (int i = 0; i < 16; ++i) q2[i] = bq[i];
        #pragma unroll 1
        for (int j = 0; j < 16; ++j) {
            float z = c_all[O_B1 + j] + cx * c_all[O_W1 + j] + cy * c_all[O_W1 + 16 + j]
                                      + cz * c_all[O_W1 + 32 + j];
            float h = lrelu(z);
            u64 h2 = pk2(h, h);
            const ulonglong2* w = (const ulonglong2*)&c_all[O_W2 + j * 32];
            #pragma unroll
            for (int i2 = 0; i2 < 8; ++i2) {
                ulonglong2 a = w[i2];
                q2[2 * i2]     = fma2_(h2, a.x, q2[2 * i2]);
                q2[2 * i2 + 1] = fma2_(h2, a.y, q2[2 * i2 + 1]);
            }
        }
        const u64* tb = (const u64*)&c_all[O_TBO];
        #pragma unroll
        for (int i = 0; i < 16; ++i) s_q[i][tid] = add2_(q2[i], tb[i]);
    }

    #pragma unroll
    for (int i = 0; i < 16; ++i) s_acc[i][tid] = 0ull;

    // ---- center row ----
    do_center(cx, cy, cz, s_q, s_u, s_acc, tid);

    // ---- 8 pairs of neighbor rows ----
    const float* obase = g_other + p * 48;
    for (int r = 0; r < 16; r += 2) {
        const float* oa = obase + r * 3;
        float xa0 = oa[0], xa1 = oa[1], xa2 = oa[2];
        float xb0 = oa[3], xb1 = oa[4], xb2 = oa[5];
        do_pair(xa0, xa1, xa2, cx - xa0, cy - xa1, cz - xa2,
                xb0, xb1, xb2, cx - xb0, cy - xb1, cz - xb2,
                s_q, s_u, s_acc, tid);
    }

    // ---- store [32] ----
    ulonglong2* outp = (ulonglong2*)&g_out[p * 32];
    #pragma unroll
    for (int i = 0; i < 8; ++i)
        outp[i] = make_ulonglong2(s_acc[2 * i][tid], s_acc[2 * i + 1][tid]);
}

#define SMEM_BYTES (64 * TPB * 8)   // 65536

extern "C" void kernel_launch(void* const* d_in, const int* in_sizes, int n_in,
                              void* d_out, int out_size) {
    const float* center = (const float*)d_in[0];
    const float* other  = (const float*)d_in[1];
    const float* w1     = (const float*)d_in[2];
    const float* b1     = (const float*)d_in[3];
    const float* w2     = (const float*)d_in[4];
    const float* b2     = (const float*)d_in[5];
    const float* wp1    = (const float*)d_in[6];
    const float* wpb1   = (const float*)d_in[7];
    const float* wp2    = (const float*)d_in[8];
    const float* wpb2   = (const float*)d_in[9];
    float* out = (float*)d_out;

    const int P = in_sizes[0] / 3;

    prep_kernel<<<1, 256>>>(w1, b1, w2, b2, wp1, wpb1, wp2, wpb2);

    void* prep_addr = nullptr;
    cudaGetSymbolAddress(&prep_addr, g_prep);
    cudaMemcpyToSymbolAsync(c_all, prep_addr, N_CONST * sizeof(float), 0,
                            cudaMemcpyDeviceToDevice, 0);

    static bool attr_set = false;
    if (!attr_set) {
        cudaFuncSetAttribute(pae_kernel, cudaFuncAttributeMaxDynamicSharedMemorySize, SMEM_BYTES);
        attr_set = true;
    }
    const int grid = (P + TPB - 1) / TPB;
    pae_kernel<<<grid, TPB, SMEM_BYTES>>>(center, other, out, P);
}